// round 1
// baseline (speedup 1.0000x reference)
#include <cuda_runtime.h>

// ---------------------------------------------------------------------------
// Problem constants (hardcoded per reference)
// ---------------------------------------------------------------------------
#define BATCH   4
#define N1      2048
#define N2      8192
#define C1      128
#define C2      64
#define KP      15
#define FOUT    128
#define NSAMP   16
#define NQ      (BATCH * N2)          // 32768 queries
#define KDIM    (KP * C1)             // 1920
#define OUTC    (FOUT + C2)           // 192

// Scratch (device globals — no runtime allocation allowed)
__device__ int   g_idx[NQ * NSAMP];           // kNN indices (within batch)
__device__ float g_wf[(size_t)NQ * KDIM];     // weighted features, row-major (q, k*C1+c)

// ---------------------------------------------------------------------------
// Kernel 1: brute-force kNN (top-16 smallest d2 among N1 points)
// One thread per query; xyz1 of the batch cached in smem (24 KB).
// ---------------------------------------------------------------------------
__global__ __launch_bounds__(256) void knn_kernel(
    const float* __restrict__ xyz1, const float* __restrict__ xyz2)
{
    __shared__ float sx[N1], sy[N1], sz[N1];
    const int b = blockIdx.y;
    const float* p1 = xyz1 + (size_t)b * N1 * 3;
    for (int i = threadIdx.x; i < N1; i += blockDim.x) {
        sx[i] = p1[i * 3 + 0];
        sy[i] = p1[i * 3 + 1];
        sz[i] = p1[i * 3 + 2];
    }
    __syncthreads();

    const int qn = blockIdx.x * blockDim.x + threadIdx.x;   // query within batch
    if (qn >= N2) return;
    const int q = b * N2 + qn;                               // global query id
    const float qx = xyz2[q * 3 + 0];
    const float qy = xyz2[q * 3 + 1];
    const float qz = xyz2[q * 3 + 2];

    float dk[NSAMP];
    int   ik[NSAMP];
    #pragma unroll
    for (int p = 0; p < NSAMP; ++p) { dk[p] = 3.4e38f; ik[p] = 0; }

    for (int j = 0; j < N1; ++j) {
        float dx = qx - sx[j];
        float dy = qy - sy[j];
        float dz = qz - sz[j];
        float d2 = dx * dx + dy * dy + dz * dz;
        if (d2 < dk[NSAMP - 1]) {                 // strict < : stable tie-break
            dk[NSAMP - 1] = d2; ik[NSAMP - 1] = j;
            #pragma unroll
            for (int p = NSAMP - 1; p > 0; --p) { // single bubble pass, static idx
                if (dk[p] < dk[p - 1]) {
                    float td = dk[p]; dk[p] = dk[p - 1]; dk[p - 1] = td;
                    int   ti = ik[p]; ik[p] = ik[p - 1]; ik[p - 1] = ti;
                }
            }
        }
    }

    int* o = g_idx + q * NSAMP;
    #pragma unroll
    for (int p = 0; p < NSAMP; ++p) o[p] = ik[p];
}

// ---------------------------------------------------------------------------
// Kernel 2: kernel-point weights + weighted feature aggregation
// One block per query, 128 threads (one per channel c).
// wf[q, k*C1 + c] = sum_s relu(1 - dist(s,k)/0.2) * feat1[idx[s], c]
// ---------------------------------------------------------------------------
__global__ __launch_bounds__(C1) void wf_kernel(
    const float* __restrict__ xyz1, const float* __restrict__ feat1,
    const float* __restrict__ xyz2, const float* __restrict__ kp)
{
    const int q = blockIdx.x;           // global query
    const int b = q >> 13;              // q / N2
    const int c = threadIdx.x;          // channel

    __shared__ int   sid[NSAMP];
    __shared__ float skp[KP * 3];
    __shared__ float sw[NSAMP][KP];

    if (c < KP * 3) skp[c] = kp[c];
    if (c < NSAMP)  sid[c] = g_idx[q * NSAMP + c];
    __syncthreads();

    if (c < NSAMP) {
        const int ni = sid[c];
        const float rx = xyz1[((size_t)b * N1 + ni) * 3 + 0] - xyz2[q * 3 + 0];
        const float ry = xyz1[((size_t)b * N1 + ni) * 3 + 1] - xyz2[q * 3 + 1];
        const float rz = xyz1[((size_t)b * N1 + ni) * 3 + 2] - xyz2[q * 3 + 2];
        #pragma unroll
        for (int k = 0; k < KP; ++k) {
            float dx = rx - skp[k * 3 + 0];
            float dy = ry - skp[k * 3 + 1];
            float dz = rz - skp[k * 3 + 2];
            float sq = dx * dx + dy * dy + dz * dz;
            float dist = sqrtf(fmaxf(sq, 1e-12f));
            sw[c][k] = fmaxf(0.0f, 1.0f - dist / 0.2f);
        }
    }
    __syncthreads();

    const float* fb = feat1 + (size_t)b * N1 * C1;
    float f[NSAMP];
    #pragma unroll
    for (int s = 0; s < NSAMP; ++s) f[s] = fb[(size_t)sid[s] * C1 + c];

    float acc[KP];
    #pragma unroll
    for (int k = 0; k < KP; ++k) acc[k] = 0.0f;
    #pragma unroll
    for (int s = 0; s < NSAMP; ++s) {
        float fs = f[s];
        #pragma unroll
        for (int k = 0; k < KP; ++k) acc[k] = fmaf(sw[s][k], fs, acc[k]);
    }

    float* wrow = g_wf + (size_t)q * KDIM + c;
    #pragma unroll
    for (int k = 0; k < KP; ++k) wrow[k * C1] = acc[k];
}

// ---------------------------------------------------------------------------
// Kernel 3: GEMM  out[q, f] = relu( sum_kc wf[q, kc] * W[kc, f] )
// M = 32768, Kd = 1920, N = 128.  128x128 block tile, BK=16, 8x8 microtile.
// ---------------------------------------------------------------------------
#define BM 128
#define BN 128
#define BK 16

__global__ __launch_bounds__(256, 2) void gemm_kernel(
    const float* __restrict__ W, float* __restrict__ out)
{
    __shared__ float As[BK][BM];   // transposed A tile
    __shared__ float Bs[BK][BN];

    const int tid = threadIdx.x;           // 0..255
    const int tx = tid & 15;                // 0..15  (N direction)
    const int ty = tid >> 4;                // 0..15  (M direction)
    const int m0 = blockIdx.x * BM;

    const float* A = g_wf;

    float acc[8][8];
    #pragma unroll
    for (int i = 0; i < 8; ++i)
        #pragma unroll
        for (int j = 0; j < 8; ++j) acc[i][j] = 0.0f;

    for (int k0 = 0; k0 < KDIM; k0 += BK) {
        // load A tile (128 rows x 16 cols) as 512 float4, transposed into smem
        #pragma unroll
        for (int i = 0; i < 2; ++i) {
            int v  = tid + i * 256;
            int r  = v >> 2;            // row 0..127
            int c4 = (v & 3) << 2;      // col 0,4,8,12
            float4 av = *(const float4*)(A + ((size_t)(m0 + r)) * KDIM + k0 + c4);
            As[c4 + 0][r] = av.x;
            As[c4 + 1][r] = av.y;
            As[c4 + 2][r] = av.z;
            As[c4 + 3][r] = av.w;
        }
        // load B tile (16 rows x 128 cols) as 512 float4
        #pragma unroll
        for (int i = 0; i < 2; ++i) {
            int v  = tid + i * 256;
            int r  = v >> 5;            // row 0..15
            int cc = (v & 31) << 2;     // col
            *(float4*)&Bs[r][cc] = *(const float4*)(W + (size_t)(k0 + r) * BN + cc);
        }
        __syncthreads();

        #pragma unroll
        for (int kk = 0; kk < BK; ++kk) {
            float a[8], bb[8];
            *(float4*)&a[0]  = *(const float4*)&As[kk][ty * 8];
            *(float4*)&a[4]  = *(const float4*)&As[kk][ty * 8 + 4];
            *(float4*)&bb[0] = *(const float4*)&Bs[kk][tx * 8];
            *(float4*)&bb[4] = *(const float4*)&Bs[kk][tx * 8 + 4];
            #pragma unroll
            for (int i = 0; i < 8; ++i)
                #pragma unroll
                for (int j = 0; j < 8; ++j)
                    acc[i][j] = fmaf(a[i], bb[j], acc[i][j]);
        }
        __syncthreads();
    }

    // epilogue: relu, write to out[m, tx*8 + j] with row stride OUTC=192
    #pragma unroll
    for (int i = 0; i < 8; ++i) {
        const size_t m = m0 + ty * 8 + i;
        float* orow = out + m * OUTC + tx * 8;
        float4 v0, v1;
        v0.x = fmaxf(acc[i][0], 0.0f); v0.y = fmaxf(acc[i][1], 0.0f);
        v0.z = fmaxf(acc[i][2], 0.0f); v0.w = fmaxf(acc[i][3], 0.0f);
        v1.x = fmaxf(acc[i][4], 0.0f); v1.y = fmaxf(acc[i][5], 0.0f);
        v1.z = fmaxf(acc[i][6], 0.0f); v1.w = fmaxf(acc[i][7], 0.0f);
        *(float4*)(orow)     = v0;
        *(float4*)(orow + 4) = v1;
    }
}

// ---------------------------------------------------------------------------
// Kernel 4: concat features2 into out[:, 128:192]
// ---------------------------------------------------------------------------
__global__ __launch_bounds__(256) void concat_kernel(
    const float* __restrict__ feat2, float* __restrict__ out)
{
    const int i = blockIdx.x * blockDim.x + threadIdx.x;   // over NQ*16 float4
    if (i >= NQ * (C2 / 4)) return;
    const int q = i >> 4;
    const int j = i & 15;
    float4 v = *(const float4*)(feat2 + (size_t)q * C2 + j * 4);
    *(float4*)(out + (size_t)q * OUTC + FOUT + j * 4) = v;
}

// ---------------------------------------------------------------------------
// Launch
// ---------------------------------------------------------------------------
extern "C" void kernel_launch(void* const* d_in, const int* in_sizes, int n_in,
                              void* d_out, int out_size)
{
    const float* xyz1  = (const float*)d_in[0];
    const float* feat1 = (const float*)d_in[1];
    const float* xyz2  = (const float*)d_in[2];
    const float* feat2 = (const float*)d_in[3];
    const float* kp    = (const float*)d_in[4];
    const float* W     = (const float*)d_in[5];
    float* out = (float*)d_out;

    knn_kernel<<<dim3(N2 / 256, BATCH), 256>>>(xyz1, xyz2);
    wf_kernel<<<NQ, C1>>>(xyz1, feat1, xyz2, kp);
    gemm_kernel<<<NQ / BM, 256>>>(W, out);
    concat_kernel<<<(NQ * (C2 / 4) + 255) / 256, 256>>>(feat2, out);
}

// round 3
// speedup vs baseline: 1.3964x; 1.3964x over previous
#include <cuda_runtime.h>
#include <cuda_bf16.h>
#include <cstdint>

// ---------------------------------------------------------------------------
// Problem constants
// ---------------------------------------------------------------------------
#define BATCH   4
#define N1      2048
#define N2      8192
#define C1      128
#define C2      64
#define KP      15
#define FOUT    128
#define NSAMP   16
#define NQ      (BATCH * N2)          // 32768 queries
#define KDIM    (KP * C1)             // 1920
#define OUTC    (FOUT + C2)           // 192
#define NCHUNK  (KDIM / 64)           // 30 K-chunks of 64 bf16

// Scratch (device globals)
__device__ int            g_idx[NQ * NSAMP];
__device__ __nv_bfloat16  g_a_hi[(size_t)NQ * KDIM];     // split wf, row-major (q, kc)
__device__ __nv_bfloat16  g_a_lo[(size_t)NQ * KDIM];
__device__ __nv_bfloat16  g_b_hi[(size_t)FOUT * KDIM];   // W^T, row-major (f, kc)
__device__ __nv_bfloat16  g_b_lo[(size_t)FOUT * KDIM];

// ---------------------------------------------------------------------------
// Helpers
// ---------------------------------------------------------------------------
__device__ __forceinline__ uint32_t smem_u32(const void* p) {
    uint32_t a;
    asm("{ .reg .u64 t; cvta.to.shared.u64 t, %1; cvt.u32.u64 %0, t; }"
        : "=r"(a) : "l"(p));
    return a;
}
// SW128 swizzle restricted to 128B rows: off = row*128 + kb (kb<128)
// -> swizzled = row*128 + (kb ^ ((row&7)<<4))

__device__ __forceinline__ void ldsm4(uint32_t* r, uint32_t addr) {
    asm volatile("ldmatrix.sync.aligned.m8n8.x4.shared.b16 {%0,%1,%2,%3}, [%4];"
                 : "=r"(r[0]), "=r"(r[1]), "=r"(r[2]), "=r"(r[3]) : "r"(addr));
}
__device__ __forceinline__ void mma16816(float* c, const uint32_t* a,
                                         const uint32_t* b) {
    asm volatile(
        "mma.sync.aligned.m16n8k16.row.col.f32.bf16.bf16.f32 "
        "{%0,%1,%2,%3}, {%4,%5,%6,%7}, {%8,%9}, {%0,%1,%2,%3};"
        : "+f"(c[0]), "+f"(c[1]), "+f"(c[2]), "+f"(c[3])
        : "r"(a[0]), "r"(a[1]), "r"(a[2]), "r"(a[3]), "r"(b[0]), "r"(b[1]));
}

// ---------------------------------------------------------------------------
// Kernel 1: brute-force kNN
// ---------------------------------------------------------------------------
__global__ __launch_bounds__(256) void knn_kernel(
    const float* __restrict__ xyz1, const float* __restrict__ xyz2)
{
    __shared__ float sx[N1], sy[N1], sz[N1];
    const int b = blockIdx.y;
    const float* p1 = xyz1 + (size_t)b * N1 * 3;
    for (int i = threadIdx.x; i < N1; i += blockDim.x) {
        sx[i] = p1[i * 3 + 0];
        sy[i] = p1[i * 3 + 1];
        sz[i] = p1[i * 3 + 2];
    }
    __syncthreads();

    const int qn = blockIdx.x * blockDim.x + threadIdx.x;
    if (qn >= N2) return;
    const int q = b * N2 + qn;
    const float qx = xyz2[q * 3 + 0];
    const float qy = xyz2[q * 3 + 1];
    const float qz = xyz2[q * 3 + 2];

    float dk[NSAMP];
    int   ik[NSAMP];
    #pragma unroll
    for (int p = 0; p < NSAMP; ++p) { dk[p] = 3.4e38f; ik[p] = 0; }

    for (int j = 0; j < N1; ++j) {
        float dx = qx - sx[j];
        float dy = qy - sy[j];
        float dz = qz - sz[j];
        float d2 = dx * dx + dy * dy + dz * dz;
        if (d2 < dk[NSAMP - 1]) {
            dk[NSAMP - 1] = d2; ik[NSAMP - 1] = j;
            #pragma unroll
            for (int p = NSAMP - 1; p > 0; --p) {
                if (dk[p] < dk[p - 1]) {
                    float td = dk[p]; dk[p] = dk[p - 1]; dk[p - 1] = td;
                    int   ti = ik[p]; ik[p] = ik[p - 1]; ik[p - 1] = ti;
                }
            }
        }
    }

    int* o = g_idx + q * NSAMP;
    #pragma unroll
    for (int p = 0; p < NSAMP; ++p) o[p] = ik[p];
}

// ---------------------------------------------------------------------------
// Kernel 2: kernel-point weights + weighted aggregation, bf16-split output
// ---------------------------------------------------------------------------
__global__ __launch_bounds__(C1) void wf_kernel(
    const float* __restrict__ xyz1, const float* __restrict__ feat1,
    const float* __restrict__ xyz2, const float* __restrict__ kp)
{
    const int q = blockIdx.x;
    const int b = q >> 13;
    const int c = threadIdx.x;

    __shared__ int   sid[NSAMP];
    __shared__ float skp[KP * 3];
    __shared__ float sw[NSAMP][KP];

    if (c < KP * 3) skp[c] = kp[c];
    if (c < NSAMP)  sid[c] = g_idx[q * NSAMP + c];
    __syncthreads();

    if (c < NSAMP) {
        const int ni = sid[c];
        const float rx = xyz1[((size_t)b * N1 + ni) * 3 + 0] - xyz2[q * 3 + 0];
        const float ry = xyz1[((size_t)b * N1 + ni) * 3 + 1] - xyz2[q * 3 + 1];
        const float rz = xyz1[((size_t)b * N1 + ni) * 3 + 2] - xyz2[q * 3 + 2];
        #pragma unroll
        for (int k = 0; k < KP; ++k) {
            float dx = rx - skp[k * 3 + 0];
            float dy = ry - skp[k * 3 + 1];
            float dz = rz - skp[k * 3 + 2];
            float sq = dx * dx + dy * dy + dz * dz;
            float dist = sqrtf(fmaxf(sq, 1e-12f));
            sw[c][k] = fmaxf(0.0f, 1.0f - dist / 0.2f);
        }
    }
    __syncthreads();

    const float* fb = feat1 + (size_t)b * N1 * C1;
    float f[NSAMP];
    #pragma unroll
    for (int s = 0; s < NSAMP; ++s) f[s] = fb[(size_t)sid[s] * C1 + c];

    float acc[KP];
    #pragma unroll
    for (int k = 0; k < KP; ++k) acc[k] = 0.0f;
    #pragma unroll
    for (int s = 0; s < NSAMP; ++s) {
        float fs = f[s];
        #pragma unroll
        for (int k = 0; k < KP; ++k) acc[k] = fmaf(sw[s][k], fs, acc[k]);
    }

    const size_t qbase = (size_t)q * KDIM + c;
    #pragma unroll
    for (int k = 0; k < KP; ++k) {
        float v = acc[k];
        __nv_bfloat16 h = __float2bfloat16(v);
        g_a_hi[qbase + k * C1] = h;
        g_a_lo[qbase + k * C1] = __float2bfloat16(v - __bfloat162float(h));
    }
}

// ---------------------------------------------------------------------------
// Kernel 2b: split + transpose W -> B^T (f, kc), bf16 hi/lo
// ---------------------------------------------------------------------------
__global__ __launch_bounds__(256) void wprep_kernel(const float* __restrict__ W)
{
    const int i = blockIdx.x * blockDim.x + threadIdx.x;
    if (i >= KDIM * FOUT) return;
    const int kc = i / FOUT;
    const int f  = i % FOUT;
    float w = W[i];
    __nv_bfloat16 h = __float2bfloat16(w);
    g_b_hi[(size_t)f * KDIM + kc] = h;
    g_b_lo[(size_t)f * KDIM + kc] = __float2bfloat16(w - __bfloat162float(h));
}

// ---------------------------------------------------------------------------
// Kernel 3: mma.sync bf16 GEMM (2-way split, 3 products), relu epilogue.
// M=32768 (256 CTAs of 128 rows), N=128, K=1920 in 30 chunks of 64.
// 8 warps in 2(M)x4(N): warp tile 64x32. Double-buffered cp.async.
// ---------------------------------------------------------------------------
#define STAGE_BYTES 65536                // 4 sub-tiles x 16KB (Ahi, Alo, Bhi, Blo)
#define SUB_BYTES   16384
#define GEMM_SMEM   (2 * STAGE_BYTES)

__global__ __launch_bounds__(256, 1)
void gemm_kernel(float* __restrict__ out)
{
    extern __shared__ __align__(1024) char dsmem[];

    const int tid = threadIdx.x;
    const int wid = tid >> 5;
    const int L   = tid & 31;
    const int m0  = blockIdx.x * 128;
    const int wm  = wid & 1;              // 0..1 (M)
    const int wn  = wid >> 1;             // 0..3 (N)

    const uint32_t base = smem_u32(dsmem);

    const char* srcA_hi = (const char*)g_a_hi + (size_t)m0 * (KDIM * 2);
    const char* srcA_lo = (const char*)g_a_lo + (size_t)m0 * (KDIM * 2);
    const char* srcB_hi = (const char*)g_b_hi;
    const char* srcB_lo = (const char*)g_b_lo;

    // cp.async: 4096 x 16B per stage / 256 thr = 16 per thread
    // thread handles rows (tid*4+v)>>3 in each 128x128B sub-tile
    auto load_stage = [&](int chunk, int buf) {
        const uint32_t sbase = base + buf * STAGE_BYTES;
        const char* srcs[4] = { srcA_hi, srcA_lo, srcB_hi, srcB_lo };
        #pragma unroll
        for (int sub = 0; sub < 4; ++sub) {
            const char* s = srcs[sub];
            #pragma unroll
            for (int v = 0; v < 4; ++v) {
                int idx = tid * 4 + v;            // 0..1023
                int row = idx >> 3;
                int kb  = (idx & 7) << 4;         // 0..112
                const char* g = s + (size_t)row * (KDIM * 2) + chunk * 128 + kb;
                uint32_t sa = sbase + sub * SUB_BYTES + row * 128
                            + (kb ^ ((row & 7) << 4));
                asm volatile("cp.async.cg.shared.global [%0], [%1], 16;"
                             :: "r"(sa), "l"(g));
            }
        }
        asm volatile("cp.async.commit_group;" ::: "memory");
    };

    // ldmatrix per-thread offsets
    // A (x4): lanes 0-7 m0-7@k0 | 8-15 m8-15@k0 | 16-23 m0-7@k8 | 24-31 m8-15@k8
    int aRow = wm * 64 + (L & 15);                  // + mt*16
    int aKb  = (L >> 4) * 16;                       // byte offset of k-half
    // B (x4): lanes 0-7 n0-7@k0 | 8-15 n0-7@k8 | 16-23 n8-15@k0 | 24-31 n8-15@k8
    int bRow = wn * 32 + ((L >> 4) << 3) + (L & 7); // + ng*16
    int bKb  = ((L >> 3) & 1) * 16;

    uint32_t aOff[4], aXor[4];
    #pragma unroll
    for (int mt = 0; mt < 4; ++mt) {
        int r = aRow + mt * 16;
        aOff[mt] = r * 128;
        aXor[mt] = (r & 7) << 4;
    }
    uint32_t bOff[2], bXor[2];
    #pragma unroll
    for (int ng = 0; ng < 2; ++ng) {
        int r = bRow + ng * 16;
        bOff[ng] = r * 128;
        bXor[ng] = (r & 7) << 4;
    }

    float acc[4][4][4];
    #pragma unroll
    for (int i = 0; i < 4; ++i)
        #pragma unroll
        for (int j = 0; j < 4; ++j)
            #pragma unroll
            for (int k = 0; k < 4; ++k) acc[i][j][k] = 0.0f;

    load_stage(0, 0);
    load_stage(1, 1);

    for (int i = 0; i < NCHUNK; ++i) {
        const int buf = i & 1;
        if (i + 1 < NCHUNK)
            asm volatile("cp.async.wait_group 1;" ::: "memory");
        else
            asm volatile("cp.async.wait_group 0;" ::: "memory");
        __syncthreads();

        const uint32_t sb  = base + buf * STAGE_BYTES;
        const uint32_t sAh = sb;
        const uint32_t sAl = sb + SUB_BYTES;
        const uint32_t sBh = sb + 2 * SUB_BYTES;
        const uint32_t sBl = sb + 3 * SUB_BYTES;

        #pragma unroll
        for (int ks = 0; ks < 4; ++ks) {
            const uint32_t kA = ks * 32 + aKb;
            const uint32_t kB = ks * 32 + bKb;
            uint32_t ah[4][4], al[4][4], bh[2][4], bl[2][4];
            #pragma unroll
            for (int mt = 0; mt < 4; ++mt) {
                uint32_t o = aOff[mt] + (kA ^ aXor[mt]);
                ldsm4(ah[mt], sAh + o);
                ldsm4(al[mt], sAl + o);
            }
            #pragma unroll
            for (int ng = 0; ng < 2; ++ng) {
                uint32_t o = bOff[ng] + (kB ^ bXor[ng]);
                ldsm4(bh[ng], sBh + o);
                ldsm4(bl[ng], sBl + o);
            }
            #pragma unroll
            for (int mt = 0; mt < 4; ++mt) {
                #pragma unroll
                for (int nt = 0; nt < 4; ++nt) {
                    const uint32_t* fh = &bh[nt >> 1][(nt & 1) * 2];
                    const uint32_t* fl = &bl[nt >> 1][(nt & 1) * 2];
                    mma16816(acc[mt][nt], ah[mt], fh);   // hi*hi
                    mma16816(acc[mt][nt], ah[mt], fl);   // hi*lo
                    mma16816(acc[mt][nt], al[mt], fh);   // lo*hi
                }
            }
        }

        __syncthreads();
        if (i + 2 < NCHUNK) load_stage(i + 2, buf);
    }

    // epilogue: relu + store (mma c-frag layout)
    #pragma unroll
    for (int mt = 0; mt < 4; ++mt) {
        #pragma unroll
        for (int nt = 0; nt < 4; ++nt) {
            const float* c = acc[mt][nt];
            int row = m0 + wm * 64 + mt * 16 + (L >> 2);
            int col = wn * 32 + nt * 8 + (L & 3) * 2;
            float2 v0, v1;
            v0.x = fmaxf(c[0], 0.0f); v0.y = fmaxf(c[1], 0.0f);
            v1.x = fmaxf(c[2], 0.0f); v1.y = fmaxf(c[3], 0.0f);
            *(float2*)(out + (size_t)row * OUTC + col)       = v0;
            *(float2*)(out + (size_t)(row + 8) * OUTC + col) = v1;
        }
    }
}

// ---------------------------------------------------------------------------
// Kernel 4: concat features2 into out[:, 128:192]
// ---------------------------------------------------------------------------
__global__ __launch_bounds__(256) void concat_kernel(
    const float* __restrict__ feat2, float* __restrict__ out)
{
    const int i = blockIdx.x * blockDim.x + threadIdx.x;
    if (i >= NQ * (C2 / 4)) return;
    const int q = i >> 4;
    const int j = i & 15;
    float4 v = *(const float4*)(feat2 + (size_t)q * C2 + j * 4);
    *(float4*)(out + (size_t)q * OUTC + FOUT + j * 4) = v;
}

// ---------------------------------------------------------------------------
// Launch
// ---------------------------------------------------------------------------
extern "C" void kernel_launch(void* const* d_in, const int* in_sizes, int n_in,
                              void* d_out, int out_size)
{
    const float* xyz1  = (const float*)d_in[0];
    const float* feat1 = (const float*)d_in[1];
    const float* xyz2  = (const float*)d_in[2];
    const float* feat2 = (const float*)d_in[3];
    const float* kp    = (const float*)d_in[4];
    const float* W     = (const float*)d_in[5];
    float* out = (float*)d_out;

    // idempotent, non-stream, capture-safe: opt into >48KB dynamic smem
    cudaFuncSetAttribute(gemm_kernel,
                         cudaFuncAttributeMaxDynamicSharedMemorySize, GEMM_SMEM);

    knn_kernel<<<dim3(N2 / 256, BATCH), 256>>>(xyz1, xyz2);
    wf_kernel<<<NQ, C1>>>(xyz1, feat1, xyz2, kp);
    wprep_kernel<<<(KDIM * FOUT + 255) / 256, 256>>>(W);
    gemm_kernel<<<NQ / 128, 256, GEMM_SMEM>>>(out);
    concat_kernel<<<(NQ * (C2 / 4) + 255) / 256, 256>>>(feat2, out);
}